// round 6
// baseline (speedup 1.0000x reference)
#include <cuda_runtime.h>
#include <cuda_fp16.h>
#include <cstdint>

#define N_ROWS 8192
#define K_DIM  512
#define J_DIM  256
#define KT     32
#define KITERS 16

// ---------------- device scratch ----------------
__device__ __half g_B[2][2][J_DIM][K_DIM];   // [mat][hi/lo][n][k], 1MB

// ---------------- smem layout (bytes) ----------------
#define BOFF   0          // B tiles: 2 stages x 81920  ([mat][h][n 256][80B])
#define RAWO   163840     // raw A fp32: 2 stages x 16384 ([mat][row 64][128B])
#define ACONV  196608     // A conv: [mat]( hi 5120 | lo 5120 ) = 20480
#define SMEM_SIZE 217088
#define EPI_STRIDE 264    // floats, epilogue staging row stride
#define EPI_E_OFF 67584   // bytes (64 * 264 * 4)

// ---------------- helpers ----------------
__device__ __forceinline__ uint32_t smem_u32(const void* p) {
    uint32_t a;
    asm("{ .reg .u64 t; cvta.to.shared.u64 t, %1; cvt.u32.u64 %0, t; }" : "=r"(a) : "l"(p));
    return a;
}
__device__ __forceinline__ void cp16(uint32_t sdst, const void* g) {
    asm volatile("cp.async.cg.shared.global [%0], [%1], 16;" :: "r"(sdst), "l"(g));
}
__device__ __forceinline__ void cp_commit() { asm volatile("cp.async.commit_group;"); }
__device__ __forceinline__ void cp_wait0()  { asm volatile("cp.async.wait_group 0;"); }

__device__ __forceinline__ void ldsm4(uint32_t (&r)[4], uint32_t addr) {
    asm volatile("ldmatrix.sync.aligned.m8n8.x4.shared.b16 {%0,%1,%2,%3}, [%4];"
        : "=r"(r[0]), "=r"(r[1]), "=r"(r[2]), "=r"(r[3]) : "r"(addr));
}
__device__ __forceinline__ void mma16816(float (&c)[4], const uint32_t (&a)[4],
                                         uint32_t b0, uint32_t b1) {
    asm volatile("mma.sync.aligned.m16n8k16.row.col.f32.f16.f16.f32 "
        "{%0,%1,%2,%3}, {%4,%5,%6,%7}, {%8,%9}, {%0,%1,%2,%3};"
        : "+f"(c[0]), "+f"(c[1]), "+f"(c[2]), "+f"(c[3])
        : "r"(a[0]), "r"(a[1]), "r"(a[2]), "r"(a[3]), "r"(b0), "r"(b1));
}
__device__ __forceinline__ uint32_t packh2(__half a, __half b) {
    __half2 h = __halves2half2(a, b);
    return *reinterpret_cast<uint32_t*>(&h);
}
__device__ __forceinline__ void split(float x, __half& hi, __half& lo) {
    hi = __float2half_rn(x);
    lo = __float2half_rn(x - __half2float(hi));
}

// ============ prep: W[512][256] -> g_B[mat][hi/lo][n][k] fp16 ============
// 256 CTAs: mat(2) x kchunk(32, 16k) x nchunk(4, 64n)
__global__ void __launch_bounds__(256)
prep_kernel(const float* __restrict__ Wu, const float* __restrict__ We)
{
    __shared__ float s[16][68];       // 272B rows: float4-aligned, low conflicts
    const int bid = blockIdx.x;
    const int m   = bid >> 7;
    const int kc  = (bid >> 2) & 31;
    const int nc  = bid & 3;
    const int k0  = kc * 16, n0 = nc * 64;
    const float* W = m ? We : Wu;
    const int tid = threadIdx.x;

    {   // load 16k x 64n tile: 256 float4, one per thread
        const int kk = tid >> 4, n4 = (tid & 15) * 4;
        *reinterpret_cast<float4*>(&s[kk][n4]) =
            *reinterpret_cast<const float4*>(&W[(size_t)(k0 + kk) * J_DIM + n0 + n4]);
    }
    __syncthreads();

    #pragma unroll
    for (int i = 0; i < 2; ++i) {
        const int o = tid + i * 256;          // 512 outputs (uint32 pairs)
        const int n = o >> 3, q = o & 7;
        const float x0 = s[2 * q][n];
        const float x1 = s[2 * q + 1][n];
        __half h0, l0, h1, l1;
        split(x0, h0, l0);
        split(x1, h1, l1);
        *reinterpret_cast<uint32_t*>(&g_B[m][0][n0 + n][k0 + 2 * q]) = packh2(h0, h1);
        *reinterpret_cast<uint32_t*>(&g_B[m][1][n0 + n][k0 + 2 * q]) = packh2(l0, l1);
    }
}

// ============ fused GEMM(U,E) + dot + sigmoid ============
// 128 CTAs, each: 64 rows x FULL 256 cols, both matrices -> out rows directly
__global__ void __launch_bounds__(256, 1)
gemm_kernel(const float* __restrict__ user, const float* __restrict__ event,
            const float* __restrict__ bu, const float* __restrict__ be,
            float* __restrict__ out)
{
    extern __shared__ __align__(1024) char smem[];
    const uint32_t sb = smem_u32(smem);
    const int tid  = threadIdx.x;
    const int wid  = tid >> 5;
    const int lane = tid & 31;
    const int m0   = blockIdx.x * 64;

    // ---- prologue: issue tile 0 ----
    {
        const int t = 0, s = 0;
        #pragma unroll
        for (int i = 0; i < 4; ++i) {
            const int e = tid + i * 256;               // 1024 A chunks
            const int mat = e >> 9, rem = e & 511, row = rem >> 3, q = rem & 7;
            const float* src = (mat ? event : user)
                             + (size_t)(m0 + row) * K_DIM + t * KT + q * 4;
            cp16(sb + RAWO + s * 16384 + mat * 8192 + row * 128 + q * 16, src);
        }
        const char* bflat = reinterpret_cast<const char*>(&g_B[0][0][0][0]);
        #pragma unroll
        for (int i = 0; i < 16; ++i) {
            const int c = tid + i * 256;               // 4096 B chunks
            const int mh = c >> 10, rem = c & 1023, n = rem >> 2, q = rem & 3;
            cp16(sb + BOFF + s * 81920 + mh * 20480 + n * 80 + q * 16,
                 bflat + (((size_t)mh * J_DIM + n) * K_DIM + t * KT) * 2 + q * 16);
        }
        cp_commit();
    }

    // warp roles: g = matrix (0=U, 1=E), wq = n-quarter (64 cols)
    const int g  = wid >> 2;
    const int wq = wid & 3;
    const uint32_t ahi_b = sb + ACONV + g * 10240;
    const uint32_t alo_b = ahi_b + 5120;
    const uint32_t a_off = (uint32_t)((lane & 15) * 80 + (lane >> 4) * 16);
    const uint32_t b_off = (uint32_t)((wq * 64 + (lane & 7) + ((lane >> 4) & 1) * 8) * 80
                                      + ((lane >> 3) & 1) * 16);

    float acc[4][8][4];
    #pragma unroll
    for (int mt = 0; mt < 4; ++mt)
        #pragma unroll
        for (int no = 0; no < 8; ++no)
            #pragma unroll
            for (int x = 0; x < 4; ++x) acc[mt][no][x] = 0.f;

    for (int t = 0; t < KITERS; ++t) {
        const int s = t & 1;
        cp_wait0();            // tile t resident
        __syncthreads();       // (a) all threads done with stage s^1 buffers

        // ---- prefetch tile t+1 into stage s^1 ----
        if (t + 1 < KITERS) {
            const int ns = s ^ 1, nt = t + 1;
            #pragma unroll
            for (int i = 0; i < 4; ++i) {
                const int e = tid + i * 256;
                const int mat = e >> 9, rem = e & 511, row = rem >> 3, q = rem & 7;
                const float* src = (mat ? event : user)
                                 + (size_t)(m0 + row) * K_DIM + nt * KT + q * 4;
                cp16(sb + RAWO + ns * 16384 + mat * 8192 + row * 128 + q * 16, src);
            }
            const char* bflat = reinterpret_cast<const char*>(&g_B[0][0][0][0]);
            #pragma unroll
            for (int i = 0; i < 16; ++i) {
                const int c = tid + i * 256;
                const int mh = c >> 10, rem = c & 1023, n = rem >> 2, q = rem & 3;
                cp16(sb + BOFF + ns * 81920 + mh * 20480 + n * 80 + q * 16,
                     bflat + (((size_t)mh * J_DIM + n) * K_DIM + nt * KT) * 2 + q * 16);
            }
            cp_commit();
        }

        // ---- convert raw A (stage s) -> fp16 hi/lo ----
        #pragma unroll
        for (int i = 0; i < 4; ++i) {
            const int e = tid + i * 256;               // 1024 float4s
            const int mat = e >> 9, rem = e & 511, row = rem >> 3, q = rem & 7;
            const float4 v = *reinterpret_cast<const float4*>(
                smem + RAWO + s * 16384 + mat * 8192 + row * 128 + q * 16);
            __half hx, lx, hy, ly, hz, lz, hw, lw;
            split(v.x, hx, lx); split(v.y, hy, ly);
            split(v.z, hz, lz); split(v.w, hw, lw);
            uint2 hv = make_uint2(packh2(hx, hy), packh2(hz, hw));
            uint2 lv = make_uint2(packh2(lx, ly), packh2(lz, lw));
            const uint32_t co = (uint32_t)(row * 80 + q * 8);
            *reinterpret_cast<uint2*>(smem + ACONV + mat * 10240 + co)        = hv;
            *reinterpret_cast<uint2*>(smem + ACONV + mat * 10240 + 5120 + co) = lv;
        }
        __syncthreads();       // (b) conversions visible

        // ---- compute ----
        const uint32_t bh_base = sb + BOFF + s * 81920 + g * 40960;
        const uint32_t bl_base = bh_base + 20480;
        #pragma unroll
        for (int ks = 0; ks < 2; ++ks) {
            const uint32_t kb = ks * 32;
            uint32_t ah[4][4], al[4][4];
            #pragma unroll
            for (int mt = 0; mt < 4; ++mt) {
                ldsm4(ah[mt], ahi_b + a_off + mt * 1280 + kb);
                ldsm4(al[mt], alo_b + a_off + mt * 1280 + kb);
            }
            #pragma unroll
            for (int ng = 0; ng < 4; ++ng) {
                uint32_t bh[4], bl[4];
                ldsm4(bh, bh_base + b_off + ng * 1280 + kb);
                ldsm4(bl, bl_base + b_off + ng * 1280 + kb);
                #pragma unroll
                for (int mt = 0; mt < 4; ++mt) {
                    mma16816(acc[mt][2 * ng],     ah[mt], bh[0], bh[1]);
                    mma16816(acc[mt][2 * ng + 1], ah[mt], bh[2], bh[3]);
                }
                #pragma unroll
                for (int mt = 0; mt < 4; ++mt) {
                    mma16816(acc[mt][2 * ng],     ah[mt], bl[0], bl[1]);
                    mma16816(acc[mt][2 * ng + 1], ah[mt], bl[2], bl[3]);
                }
                #pragma unroll
                for (int mt = 0; mt < 4; ++mt) {
                    mma16816(acc[mt][2 * ng],     al[mt], bh[0], bh[1]);
                    mma16816(acc[mt][2 * ng + 1], al[mt], bh[2], bh[3]);
                }
            }
        }
    }

    // ---- epilogue: stage both 64x256 fp32 tiles in smem (reuse B region) ----
    __syncthreads();
    float* ep = reinterpret_cast<float*>(smem + (g ? EPI_E_OFF : 0));
    #pragma unroll
    for (int mt = 0; mt < 4; ++mt) {
        #pragma unroll
        for (int no = 0; no < 8; ++no) {
            const int row = mt * 16 + (lane >> 2);
            const int col = wq * 64 + no * 8 + (lane & 3) * 2;
            *reinterpret_cast<float2*>(&ep[row * EPI_STRIDE + col]) =
                make_float2(acc[mt][no][0], acc[mt][no][1]);
            *reinterpret_cast<float2*>(&ep[(row + 8) * EPI_STRIDE + col]) =
                make_float2(acc[mt][no][2], acc[mt][no][3]);
        }
    }
    __syncthreads();

    // ---- fused dot + bias + sigmoid: 4 threads per row ----
    {
        const float* Us = reinterpret_cast<const float*>(smem);
        const float* Es = reinterpret_cast<const float*>(smem + EPI_E_OFF);
        const int row = tid >> 2;
        const int t4  = tid & 3;
        float ssum = 0.f;
        #pragma unroll
        for (int j = 0; j < 16; ++j) {
            const int col = t4 * 64 + j * 4;
            const float4 u  = *reinterpret_cast<const float4*>(&Us[row * EPI_STRIDE + col]);
            const float4 e  = *reinterpret_cast<const float4*>(&Es[row * EPI_STRIDE + col]);
            const float4 b1 = *reinterpret_cast<const float4*>(&bu[col]);
            const float4 b2 = *reinterpret_cast<const float4*>(&be[col]);
            ssum += (u.x + b1.x) * (e.x + b2.x)
                  + (u.y + b1.y) * (e.y + b2.y)
                  + (u.z + b1.z) * (e.z + b2.z)
                  + (u.w + b1.w) * (e.w + b2.w);
        }
        ssum += __shfl_xor_sync(0xffffffffu, ssum, 1);
        ssum += __shfl_xor_sync(0xffffffffu, ssum, 2);
        if (t4 == 0)
            out[m0 + row] = 1.0f / (1.0f + expf(-ssum));
    }
}

extern "C" void kernel_launch(void* const* d_in, const int* in_sizes, int n_in,
                              void* d_out, int out_size)
{
    const float* user  = (const float*)d_in[0];
    const float* event = (const float*)d_in[1];
    const float* Wu    = (const float*)d_in[2];
    const float* bu    = (const float*)d_in[3];
    const float* We    = (const float*)d_in[4];
    const float* be    = (const float*)d_in[5];
    float* out = (float*)d_out;

    cudaFuncSetAttribute(gemm_kernel, cudaFuncAttributeMaxDynamicSharedMemorySize, SMEM_SIZE);

    prep_kernel<<<256, 256>>>(Wu, We);
    gemm_kernel<<<128, 256, SMEM_SIZE>>>(user, event, bu, be, out);
}

// round 7
// speedup vs baseline: 1.0598x; 1.0598x over previous
#include <cuda_runtime.h>
#include <cuda_fp16.h>
#include <cstdint>

#define N_ROWS 8192
#define K_DIM  512
#define J_DIM  256
#define KT     32
#define KITERS 16

// ---------------- device scratch ----------------
__device__ __half g_B[2][2][J_DIM][K_DIM];   // [mat][hi/lo][n][k], 1MB
__device__ float  g_part[2][N_ROWS];

// ---------------- smem layout (bytes) ----------------
// B: 2 stages x [mat][hilo][n 128][80B] = 2 x 40960 = 81920
// ACONV: [mat][hilo][row 64][80B] = 20480 @ 81920
#define ACONV  81920
#define SMEM_SIZE 102400
#define EPI_STRIDE 136            // floats
#define EPI_E_OFF  34816          // bytes = 64*136*4

// ---------------- helpers ----------------
__device__ __forceinline__ uint32_t smem_u32(const void* p) {
    uint32_t a;
    asm("{ .reg .u64 t; cvta.to.shared.u64 t, %1; cvt.u32.u64 %0, t; }" : "=r"(a) : "l"(p));
    return a;
}
__device__ __forceinline__ void cp16(uint32_t sdst, const void* g) {
    asm volatile("cp.async.cg.shared.global [%0], [%1], 16;" :: "r"(sdst), "l"(g));
}
__device__ __forceinline__ void cp_commit() { asm volatile("cp.async.commit_group;"); }
template <int N>
__device__ __forceinline__ void cp_wait() { asm volatile("cp.async.wait_group %0;" :: "n"(N)); }

__device__ __forceinline__ void ldsm4(uint32_t (&r)[4], uint32_t addr) {
    asm volatile("ldmatrix.sync.aligned.m8n8.x4.shared.b16 {%0,%1,%2,%3}, [%4];"
        : "=r"(r[0]), "=r"(r[1]), "=r"(r[2]), "=r"(r[3]) : "r"(addr));
}
__device__ __forceinline__ void mma16816(float (&c)[4], const uint32_t (&a)[4],
                                         uint32_t b0, uint32_t b1) {
    asm volatile("mma.sync.aligned.m16n8k16.row.col.f32.f16.f16.f32 "
        "{%0,%1,%2,%3}, {%4,%5,%6,%7}, {%8,%9}, {%0,%1,%2,%3};"
        : "+f"(c[0]), "+f"(c[1]), "+f"(c[2]), "+f"(c[3])
        : "r"(a[0]), "r"(a[1]), "r"(a[2]), "r"(a[3]), "r"(b0), "r"(b1));
}
__device__ __forceinline__ uint32_t packh2(__half a, __half b) {
    __half2 h = __halves2half2(a, b);
    return *reinterpret_cast<uint32_t*>(&h);
}
__device__ __forceinline__ void split(float x, __half& hi, __half& lo) {
    hi = __float2half_rn(x);
    lo = __float2half_rn(x - __half2float(hi));
}

// ============ prep: W[512][256] -> g_B[mat][hi/lo][n][k] fp16 ============
__global__ void __launch_bounds__(256)
prep_kernel(const float* __restrict__ Wu, const float* __restrict__ We)
{
    __shared__ float s[16][68];
    const int bid = blockIdx.x;
    const int m   = bid >> 7;
    const int kc  = (bid >> 2) & 31;
    const int nc  = bid & 3;
    const int k0  = kc * 16, n0 = nc * 64;
    const float* W = m ? We : Wu;
    const int tid = threadIdx.x;

    {
        const int kk = tid >> 4, n4 = (tid & 15) * 4;
        *reinterpret_cast<float4*>(&s[kk][n4]) =
            *reinterpret_cast<const float4*>(&W[(size_t)(k0 + kk) * J_DIM + n0 + n4]);
    }
    __syncthreads();

    #pragma unroll
    for (int i = 0; i < 2; ++i) {
        const int o = tid + i * 256;
        const int n = o >> 3, q = o & 7;
        const float x0 = s[2 * q][n];
        const float x1 = s[2 * q + 1][n];
        __half h0, l0, h1, l1;
        split(x0, h0, l0);
        split(x1, h1, l1);
        *reinterpret_cast<uint32_t*>(&g_B[m][0][n0 + n][k0 + 2 * q]) = packh2(h0, h1);
        *reinterpret_cast<uint32_t*>(&g_B[m][1][n0 + n][k0 + 2 * q]) = packh2(l0, l1);
    }
}

// ============ GEMM: 256 CTAs (mtile 128 x ntile 2), 64 rows x 128 cols ============
__global__ void __launch_bounds__(256, 2)
gemm_kernel(const float* __restrict__ user, const float* __restrict__ event,
            const float* __restrict__ bu, const float* __restrict__ be)
{
    extern __shared__ __align__(1024) char smem[];
    const uint32_t sb = smem_u32(smem);
    const int tid  = threadIdx.x;
    const int wid  = tid >> 5;
    const int lane = tid & 31;

    const int mtile = blockIdx.x >> 1;
    const int ntile = blockIdx.x & 1;
    const int m0 = mtile * 64;
    const int n0 = ntile * 128;

    // A direct-load indices: 4 float4 per thread (both mats)
    // e = tid + i*256: mat = e>>9, row = (e&511)>>3, q = e&7
    const int a_mat0 = tid >> 9;            // always 0 for tid<256; use per-i mat below
    (void)a_mat0;

    // B cp.async: 8 chunks per thread per stage
    const char* bflat = reinterpret_cast<const char*>(&g_B[0][0][0][0]);

    // ---- prologue ----
    {
        const int t = 0, s = 0;
        #pragma unroll
        for (int i = 0; i < 8; ++i) {
            const int c = tid + i * 256;        // 2048 chunks
            const int nrow = c >> 2, q = c & 3; // nrow: [mat*2+h]*128 + n
            const int mat = nrow >> 8, h = (nrow >> 7) & 1, n = nrow & 127;
            cp16(sb + s * 40960 + nrow * 80 + q * 16,
                 bflat + (((size_t)(mat * 2 + h) * J_DIM + n0 + n) * K_DIM + t * KT) * 2
                       + q * 16);
        }
        cp_commit();
    }

    float4 Abuf[4];
    #pragma unroll
    for (int i = 0; i < 4; ++i) {
        const int e = tid + i * 256;
        const int mat = e >> 9, rem = e & 511, row = rem >> 3, q = rem & 7;
        Abuf[i] = *reinterpret_cast<const float4*>(
            (mat ? event : user) + (size_t)(m0 + row) * K_DIM + 0 * KT + q * 4);
    }

    // warp roles: g = mat, wm = 32-row half, wn = 64-col half
    const int g  = wid >> 2;
    const int wm = (wid >> 1) & 1;
    const int wn = wid & 1;
    const uint32_t ahi_b = sb + ACONV + g * 10240;
    const uint32_t alo_b = ahi_b + 5120;
    const uint32_t a_off = (uint32_t)((wm * 32 + (lane & 15)) * 80 + (lane >> 4) * 16);
    const uint32_t b_off = (uint32_t)((wn * 64 + (lane & 7) + ((lane >> 4) & 1) * 8) * 80
                                      + ((lane >> 3) & 1) * 16);

    float acc[2][8][4];
    #pragma unroll
    for (int mt = 0; mt < 2; ++mt)
        #pragma unroll
        for (int no = 0; no < 8; ++no)
            #pragma unroll
            for (int x = 0; x < 4; ++x) acc[mt][no][x] = 0.f;

    for (int t = 0; t < KITERS; ++t) {
        const int s = t & 1;

        // 1. issue B(t+1)
        if (t + 1 < KITERS) {
            const int ns = s ^ 1, nt = t + 1;
            #pragma unroll
            for (int i = 0; i < 8; ++i) {
                const int c = tid + i * 256;
                const int nrow = c >> 2, q = c & 3;
                const int mat = nrow >> 8, h = (nrow >> 7) & 1, n = nrow & 127;
                cp16(sb + ns * 40960 + nrow * 80 + q * 16,
                     bflat + (((size_t)(mat * 2 + h) * J_DIM + n0 + n) * K_DIM + nt * KT) * 2
                           + q * 16);
            }
            cp_commit();
        }

        // 2. convert Abuf(t) -> ACONV smem
        #pragma unroll
        for (int i = 0; i < 4; ++i) {
            const int e = tid + i * 256;
            const int mat = e >> 9, rem = e & 511, row = rem >> 3, q = rem & 7;
            const float4 v = Abuf[i];
            __half hx, lx, hy, ly, hz, lz, hw, lw;
            split(v.x, hx, lx); split(v.y, hy, ly);
            split(v.z, hz, lz); split(v.w, hw, lw);
            uint2 hv = make_uint2(packh2(hx, hy), packh2(hz, hw));
            uint2 lv = make_uint2(packh2(lx, ly), packh2(lz, lw));
            const uint32_t co = (uint32_t)(row * 80 + q * 8);
            *reinterpret_cast<uint2*>(smem + ACONV + mat * 10240 + co)        = hv;
            *reinterpret_cast<uint2*>(smem + ACONV + mat * 10240 + 5120 + co) = lv;
        }

        // 3. prefetch A(t+1) into regs
        if (t + 1 < KITERS) {
            #pragma unroll
            for (int i = 0; i < 4; ++i) {
                const int e = tid + i * 256;
                const int mat = e >> 9, rem = e & 511, row = rem >> 3, q = rem & 7;
                Abuf[i] = *reinterpret_cast<const float4*>(
                    (mat ? event : user) + (size_t)(m0 + row) * K_DIM + (t + 1) * KT + q * 4);
            }
        }

        // 4. wait B(t), 5. barrier
        if (t + 1 < KITERS) cp_wait<1>(); else cp_wait<0>();
        __syncthreads();

        // 6. compute
        const uint32_t bh_base = sb + s * 40960 + g * 20480;
        const uint32_t bl_base = bh_base + 10240;
        #pragma unroll
        for (int ks = 0; ks < 2; ++ks) {
            const uint32_t kb = ks * 32;
            uint32_t ah[2][4], al[2][4];
            #pragma unroll
            for (int mt = 0; mt < 2; ++mt) {
                ldsm4(ah[mt], ahi_b + a_off + mt * 1280 + kb);
                ldsm4(al[mt], alo_b + a_off + mt * 1280 + kb);
            }
            #pragma unroll
            for (int ng = 0; ng < 4; ++ng) {
                uint32_t bh[4], bl[4];
                ldsm4(bh, bh_base + b_off + ng * 1280 + kb);
                ldsm4(bl, bl_base + b_off + ng * 1280 + kb);
                #pragma unroll
                for (int mt = 0; mt < 2; ++mt) {
                    mma16816(acc[mt][2 * ng],     ah[mt], bh[0], bh[1]);
                    mma16816(acc[mt][2 * ng + 1], ah[mt], bh[2], bh[3]);
                    mma16816(acc[mt][2 * ng],     ah[mt], bl[0], bl[1]);
                    mma16816(acc[mt][2 * ng + 1], ah[mt], bl[2], bl[3]);
                    mma16816(acc[mt][2 * ng],     al[mt], bh[0], bh[1]);
                    mma16816(acc[mt][2 * ng + 1], al[mt], bh[2], bh[3]);
                }
            }
        }

        // 7. barrier: ACONV + B stage reads done
        __syncthreads();
    }

    // ---- epilogue: stage 64x128 fp32 tiles (reuse B region) ----
    float* ep = reinterpret_cast<float*>(smem + (g ? EPI_E_OFF : 0));
    #pragma unroll
    for (int mt = 0; mt < 2; ++mt) {
        #pragma unroll
        for (int no = 0; no < 8; ++no) {
            const int row = wm * 32 + mt * 16 + (lane >> 2);
            const int col = wn * 64 + no * 8 + (lane & 3) * 2;
            *reinterpret_cast<float2*>(&ep[row * EPI_STRIDE + col]) =
                make_float2(acc[mt][no][0], acc[mt][no][1]);
            *reinterpret_cast<float2*>(&ep[(row + 8) * EPI_STRIDE + col]) =
                make_float2(acc[mt][no][2], acc[mt][no][3]);
        }
    }
    __syncthreads();

    // ---- partial dot (with biases) over this CTA's 128 cols ----
    {
        const float* Us = reinterpret_cast<const float*>(smem);
        const float* Es = reinterpret_cast<const float*>(smem + EPI_E_OFF);
        const int row = tid >> 2;
        const int t4  = tid & 3;
        float ssum = 0.f;
        #pragma unroll
        for (int j = 0; j < 8; ++j) {
            const int col = t4 * 32 + j * 4;
            const float4 u  = *reinterpret_cast<const float4*>(&Us[row * EPI_STRIDE + col]);
            const float4 e  = *reinterpret_cast<const float4*>(&Es[row * EPI_STRIDE + col]);
            const float4 b1 = *reinterpret_cast<const float4*>(&bu[n0 + col]);
            const float4 b2 = *reinterpret_cast<const float4*>(&be[n0 + col]);
            ssum += (u.x + b1.x) * (e.x + b2.x)
                  + (u.y + b1.y) * (e.y + b2.y)
                  + (u.z + b1.z) * (e.z + b2.z)
                  + (u.w + b1.w) * (e.w + b2.w);
        }
        ssum += __shfl_xor_sync(0xffffffffu, ssum, 1);
        ssum += __shfl_xor_sync(0xffffffffu, ssum, 2);
        if (t4 == 0)
            g_part[ntile][m0 + row] = ssum;
    }
}

// ============ combine ============
__global__ void __launch_bounds__(256)
combine_kernel(float* __restrict__ out)
{
    const int i = blockIdx.x * 256 + threadIdx.x;
    const float l = g_part[0][i] + g_part[1][i];
    out[i] = 1.0f / (1.0f + expf(-l));
}

extern "C" void kernel_launch(void* const* d_in, const int* in_sizes, int n_in,
                              void* d_out, int out_size)
{
    const float* user  = (const float*)d_in[0];
    const float* event = (const float*)d_in[1];
    const float* Wu    = (const float*)d_in[2];
    const float* bu    = (const float*)d_in[3];
    const float* We    = (const float*)d_in[4];
    const float* be    = (const float*)d_in[5];
    float* out = (float*)d_out;

    cudaFuncSetAttribute(gemm_kernel, cudaFuncAttributeMaxDynamicSharedMemorySize, SMEM_SIZE);

    prep_kernel<<<256, 256>>>(Wu, We);
    gemm_kernel<<<256, 256, SMEM_SIZE>>>(user, event, bu, be);
    combine_kernel<<<N_ROWS / 256, 256>>>(out);
}